// round 2
// baseline (speedup 1.0000x reference)
#include <cuda_runtime.h>
#include <math.h>

#define HW    16384
#define WID   128
#define CCH   192
#define C3    576
#define NB    8
#define NHEAD 4
#define CH    48
#define EPSV  1e-12f

// ---------------- scratch (device globals; allocation-free) ----------------
__device__ __align__(16) float g_cn1 [(size_t)NB*CCH*HW];  // conv1x1(cn)
__device__ __align__(16) float g_cnf [(size_t)NB*CCH*HW];  // conv3x3(g_cn1)
__device__ __align__(16) float g_qkv1[(size_t)NB*C3 *HW];  // conv1x1(x)
__device__ __align__(16) float g_qkv [(size_t)NB*C3 *HW];  // depthwise(g_qkv1)
__device__ __align__(16) float g_qf  [(size_t)NB*CCH*HW];  // final normalized q
__device__ __align__(16) float g_kn  [(size_t)NB*CCH*HW];  // normalized k
__device__ __align__(16) float g_av  [(size_t)NB*CCH*HW];  // attn @ v
__device__ float g_alpha[NB*CCH];
__device__ float g_beta [NB*CCH];
__device__ float g_invk [NB*CCH];
__device__ float g_Lpart[(size_t)16*NB*NHEAD*CH*CH];       // deterministic partials
__device__ float g_attn [(size_t)NB*NHEAD*CH*CH];

// ---------------- 1x1 conv == SGEMM: Y[b,m,s] = sum_k W[m,k] X[b,k,s] -------
// BM=BN=64, BK=16, 256 threads, 4x4 microtile. M,K,N all divide tiles evenly.
__global__ __launch_bounds__(256) void gemm1x1_k(
    const float* __restrict__ Wm, const float* __restrict__ X,
    float* __restrict__ Y, int M, int K)
{
  const int b  = blockIdx.z;
  const int m0 = blockIdx.y * 64;
  const int n0 = blockIdx.x * 64;
  const float* Xb = X + (size_t)b * K * HW;
  float* Yb = Y + (size_t)b * M * HW;
  __shared__ float As[16][64];
  __shared__ float Bs[16][64];
  const int t  = threadIdx.x;
  const int tx = t & 15, ty = t >> 4;
  float acc[4][4] = {};
  for (int k0 = 0; k0 < K; k0 += 16) {
    {
      int ma = t >> 2;
      int ka = (t & 3) * 4;
      float4 a4 = *(const float4*)&Wm[(size_t)(m0+ma)*K + k0 + ka];
      As[ka+0][ma]=a4.x; As[ka+1][ma]=a4.y; As[ka+2][ma]=a4.z; As[ka+3][ma]=a4.w;
    }
    {
      int kb = t >> 4;
      int nb = (t & 15) * 4;
      *(float4*)&Bs[kb][nb] = *(const float4*)&Xb[(size_t)(k0+kb)*HW + n0 + nb];
    }
    __syncthreads();
    #pragma unroll
    for (int k = 0; k < 16; k++) {
      float a0 = As[k][ty*4+0], a1 = As[k][ty*4+1];
      float a2 = As[k][ty*4+2], a3 = As[k][ty*4+3];
      float4 bv = *(float4*)&Bs[k][tx*4];
      acc[0][0]+=a0*bv.x; acc[0][1]+=a0*bv.y; acc[0][2]+=a0*bv.z; acc[0][3]+=a0*bv.w;
      acc[1][0]+=a1*bv.x; acc[1][1]+=a1*bv.y; acc[1][2]+=a1*bv.z; acc[1][3]+=a1*bv.w;
      acc[2][0]+=a2*bv.x; acc[2][1]+=a2*bv.y; acc[2][2]+=a2*bv.z; acc[2][3]+=a2*bv.w;
      acc[3][0]+=a3*bv.x; acc[3][1]+=a3*bv.y; acc[3][2]+=a3*bv.z; acc[3][3]+=a3*bv.w;
    }
    __syncthreads();
  }
  #pragma unroll
  for (int i = 0; i < 4; i++) {
    float4 o = make_float4(acc[i][0],acc[i][1],acc[i][2],acc[i][3]);
    *(float4*)&Yb[(size_t)(m0+ty*4+i)*HW + n0 + tx*4] = o;
  }
}

// ---------------- 3x3 conv as implicit GEMM, K=192*9=1728 ------------------
// Weight layout [co][ci][dy][dx] is exactly row-major over k=ci*9+dy*3+dx.
// Each 64-wide N tile lies in a single image row (16384%128==0, n0%64==0).
__global__ __launch_bounds__(256) void conv3x3_k(
    const float* __restrict__ Wm, const float* __restrict__ X,
    float* __restrict__ Y)
{
  const int Ktot = CCH * 9;
  const int b  = blockIdx.z;
  const int m0 = blockIdx.y * 64;
  const int n0 = blockIdx.x * 64;
  const float* Xb = X + (size_t)b * CCH * HW;
  float* Yb = Y + (size_t)b * CCH * HW;
  __shared__ float As[16][64];
  __shared__ float Bs[16][64];
  const int t  = threadIdx.x;
  const int tx = t & 15, ty = t >> 4;
  const int y  = n0 >> 7;          // whole tile in one image row
  const int x0t = n0 & 127;
  float acc[4][4] = {};
  for (int k0 = 0; k0 < Ktot; k0 += 16) {
    {
      int ma = t >> 2;
      int ka = (t & 3) * 4;
      float4 a4 = *(const float4*)&Wm[(size_t)(m0+ma)*Ktot + k0 + ka];
      As[ka+0][ma]=a4.x; As[ka+1][ma]=a4.y; As[ka+2][ma]=a4.z; As[ka+3][ma]=a4.w;
    }
    {
      int kb = t >> 4;              // 0..15
      int kk = k0 + kb;
      int ci = kk / 9;
      int r  = kk - ci * 9;
      int dy = r / 3 - 1;
      int dx = r - (r / 3) * 3 - 1;
      int yy = y + dy;
      bool rowok = (yy >= 0) & (yy < WID);
      const float* src = Xb + (size_t)ci * HW + yy * WID;
      int nb = (t & 15) * 4;
      #pragma unroll
      for (int j = 0; j < 4; j++) {
        int xx = x0t + nb + j + dx;
        float v = 0.f;
        if (rowok && xx >= 0 && xx < WID) v = src[xx];
        Bs[kb][nb + j] = v;
      }
    }
    __syncthreads();
    #pragma unroll
    for (int k = 0; k < 16; k++) {
      float a0 = As[k][ty*4+0], a1 = As[k][ty*4+1];
      float a2 = As[k][ty*4+2], a3 = As[k][ty*4+3];
      float4 bv = *(float4*)&Bs[k][tx*4];
      acc[0][0]+=a0*bv.x; acc[0][1]+=a0*bv.y; acc[0][2]+=a0*bv.z; acc[0][3]+=a0*bv.w;
      acc[1][0]+=a1*bv.x; acc[1][1]+=a1*bv.y; acc[1][2]+=a1*bv.z; acc[1][3]+=a1*bv.w;
      acc[2][0]+=a2*bv.x; acc[2][1]+=a2*bv.y; acc[2][2]+=a2*bv.z; acc[2][3]+=a2*bv.w;
      acc[3][0]+=a3*bv.x; acc[3][1]+=a3*bv.y; acc[3][2]+=a3*bv.z; acc[3][3]+=a3*bv.w;
    }
    __syncthreads();
  }
  #pragma unroll
  for (int i = 0; i < 4; i++) {
    float4 o = make_float4(acc[i][0],acc[i][1],acc[i][2],acc[i][3]);
    *(float4*)&Yb[(size_t)(m0+ty*4+i)*HW + n0 + tx*4] = o;
  }
}

// ---------------- depthwise 3x3 (groups = 3C) -------------------------------
__global__ __launch_bounds__(256) void dwconv3_k(
    const float* __restrict__ in, const float* __restrict__ w,
    float* __restrict__ out)
{
  size_t idx = (size_t)blockIdx.x * 256 + threadIdx.x;  // B*576*HW threads
  int s = (int)(idx & (HW - 1));
  size_t cb = idx >> 14;          // b*576 + c
  int c = (int)(cb % C3);
  int y = s >> 7, x = s & 127;
  const float* wp = w + (size_t)c * 9;
  const float* ip = in + (idx - s);
  float acc = 0.f;
  #pragma unroll
  for (int dy = -1; dy <= 1; dy++) {
    int yy = y + dy;
    if (yy < 0 || yy >= WID) continue;
    #pragma unroll
    for (int dx = -1; dx <= 1; dx++) {
      int xx = x + dx;
      if (xx < 0 || xx >= WID) continue;
      acc += wp[(dy+1)*3 + dx + 1] * ip[yy*WID + xx];
    }
  }
  out[idx] = acc;
}

// ---------------- per-(b,c) norms + fold double-normalize into scalars -----
__global__ __launch_bounds__(256) void rownorms_k(
    const float* __restrict__ qkv, const float* __restrict__ cnf,
    float* __restrict__ alpha, float* __restrict__ beta,
    float* __restrict__ invk)
{
  int c = blockIdx.x, b = blockIdx.y;
  const float* q  = qkv + ((size_t)b*C3 + c) * HW;
  const float* k  = qkv + ((size_t)b*C3 + CCH + c) * HW;
  const float* cn = cnf + ((size_t)b*CCH + c) * HW;
  float sq = 0, sk = 0, sc = 0, sd = 0;
  for (int s = threadIdx.x; s < HW; s += 256) {
    float qv = q[s], kv = k[s], cv = cn[s];
    sq += qv*qv; sk += kv*kv; sc += cv*cv; sd += qv*cv;
  }
  #pragma unroll
  for (int o = 16; o > 0; o >>= 1) {
    sq += __shfl_down_sync(0xffffffffu, sq, o);
    sk += __shfl_down_sync(0xffffffffu, sk, o);
    sc += __shfl_down_sync(0xffffffffu, sc, o);
    sd += __shfl_down_sync(0xffffffffu, sd, o);
  }
  __shared__ float red[4][8];
  int lane = threadIdx.x & 31, wid = threadIdx.x >> 5;
  if (lane == 0) { red[0][wid]=sq; red[1][wid]=sk; red[2][wid]=sc; red[3][wid]=sd; }
  __syncthreads();
  if (threadIdx.x == 0) {
    float Sq=0, Sk=0, Sc=0, Sd=0;
    for (int i = 0; i < 8; i++) { Sq+=red[0][i]; Sk+=red[1][i]; Sc+=red[2][i]; Sd+=red[3][i]; }
    float a  = fmaxf(sqrtf(Sq), EPSV);
    float bb = fmaxf(sqrtf(Sc), EPSV);
    float n2 = Sq/(a*a) + 2.f*Sd/(a*bb) + Sc/(bb*bb);   // ||q/a + cn/bb||^2
    float dn = fmaxf(sqrtf(fmaxf(n2, 0.f)), EPSV);
    int bc = b*CCH + c;
    alpha[bc] = 1.f / (a * dn);
    beta [bc] = 1.f / (bb * dn);
    invk [bc] = 1.f / fmaxf(sqrtf(Sk), EPSV);
  }
}

// ---------------- materialize qf = a*q + b*cn, kn = invk*k ------------------
__global__ __launch_bounds__(256) void make_qfkn_k(
    const float* __restrict__ qkv, const float* __restrict__ cnf,
    const float* __restrict__ alpha, const float* __restrict__ beta,
    const float* __restrict__ invk,
    float* __restrict__ qf, float* __restrict__ kn)
{
  size_t idx = (size_t)blockIdx.x * 256 + threadIdx.x;  // B*192*HW threads
  int s = (int)(idx & (HW - 1));
  size_t bc = idx >> 14;          // b*192 + c
  int b = (int)(bc / CCH);
  int c = (int)(bc % CCH);
  const float* qkvb = qkv + (size_t)b * C3 * HW;
  float qv = qkvb[(size_t)c * HW + s];
  float kv = qkvb[(size_t)(CCH + c) * HW + s];
  float cv = cnf[idx];
  qf[idx] = alpha[bc] * qv + beta[bc] * cv;
  kn[idx] = invk[bc] * kv;
}

// ---------------- logits partials: L[c,d] = sum_s qf[c,s] kn[d,s] -----------
// grid (16 s-chunks, 32 bh). Deterministic: each chunk writes its own slab.
__global__ __launch_bounds__(256) void logits_k(
    const float* __restrict__ qf, const float* __restrict__ kn,
    float* __restrict__ Lpart)
{
  int bh = blockIdx.y; int b = bh >> 2, h = bh & 3;
  int chunk = blockIdx.x;
  int s0 = chunk * 1024;
  const float* Q = qf + ((size_t)b*CCH + h*CH) * HW;
  const float* K = kn + ((size_t)b*CCH + h*CH) * HW;
  __shared__ float Qs[48][68];   // stride 68 floats: 16B aligned + reduces conflicts
  __shared__ float Ks[48][68];
  const int t = threadIdx.x;
  const int tx = t & 15, ty = t >> 4;
  float acc[3][3] = {};
  for (int sc = 0; sc < 1024; sc += 64) {
    #pragma unroll
    for (int i = 0; i < 3; i++) {
      int e = t + i * 256;           // 0..767 float4 slot
      int row = e >> 4;
      int col = (e & 15) * 4;
      *(float4*)&Qs[row][col] = *(const float4*)&Q[(size_t)row*HW + s0 + sc + col];
      *(float4*)&Ks[row][col] = *(const float4*)&K[(size_t)row*HW + s0 + sc + col];
    }
    __syncthreads();
    #pragma unroll 8
    for (int s = 0; s < 64; s++) {
      float qv0 = Qs[ty*3+0][s], qv1 = Qs[ty*3+1][s], qv2 = Qs[ty*3+2][s];
      float kv0 = Ks[tx*3+0][s], kv1 = Ks[tx*3+1][s], kv2 = Ks[tx*3+2][s];
      acc[0][0]+=qv0*kv0; acc[0][1]+=qv0*kv1; acc[0][2]+=qv0*kv2;
      acc[1][0]+=qv1*kv0; acc[1][1]+=qv1*kv1; acc[1][2]+=qv1*kv2;
      acc[2][0]+=qv2*kv0; acc[2][1]+=qv2*kv1; acc[2][2]+=qv2*kv2;
    }
    __syncthreads();
  }
  float* Lp = Lpart + (((size_t)chunk * 32 + bh) * CH) * CH;
  #pragma unroll
  for (int i = 0; i < 3; i++)
    #pragma unroll
    for (int j = 0; j < 3; j++)
      Lp[(size_t)(ty*3+i)*CH + tx*3+j] = acc[i][j];
}

// ---------------- reduce partials + temperature + softmax over d ------------
__global__ __launch_bounds__(32) void softmax_k(
    const float* __restrict__ Lpart, const float* __restrict__ temp,
    float* __restrict__ attn)
{
  int row = blockIdx.x;            // bh*48 + c
  int bh = row / CH;
  int c  = row - bh * CH;
  int h  = bh & 3;
  int lane = threadIdx.x;
  float tv = temp[h];
  float v0 = 0.f, v1 = 0.f;
  bool has1 = (lane + 32) < CH;    // lanes 0..15
  for (int ch = 0; ch < 16; ch++) {
    const float* p = Lpart + (((size_t)ch*32 + bh)*CH + c)*CH;
    v0 += p[lane];
    if (has1) v1 += p[lane + 32];
  }
  v0 *= tv; v1 *= tv;
  float m = has1 ? fmaxf(v0, v1) : v0;
  #pragma unroll
  for (int o = 16; o > 0; o >>= 1) m = fmaxf(m, __shfl_xor_sync(0xffffffffu, m, o));
  float e0 = __expf(v0 - m);
  float e1 = has1 ? __expf(v1 - m) : 0.f;
  float s = e0 + e1;
  #pragma unroll
  for (int o = 16; o > 0; o >>= 1) s += __shfl_xor_sync(0xffffffffu, s, o);
  float inv = 1.f / s;
  attn[(size_t)row*CH + lane] = e0 * inv;
  if (has1) attn[(size_t)row*CH + lane + 32] = e1 * inv;
}

// ---------------- out[c,s] = sum_d attn[c,d] * v[d,s] -----------------------
__global__ __launch_bounds__(256) void attnv_k(
    const float* __restrict__ qkv, const float* __restrict__ attn,
    float* __restrict__ out)
{
  int bh = blockIdx.z; int b = bh >> 2, h = bh & 3;
  int cg = blockIdx.y;             // 0..5 -> 8 channels each
  int s0 = blockIdx.x * 1024;
  __shared__ float a_s[8][48];
  const int t = threadIdx.x;
  for (int e = t; e < 8*48; e += 256)
    a_s[e/48][e%48] = attn[((size_t)bh*CH + cg*8 + e/48)*CH + (e%48)];
  __syncthreads();
  const float* V = qkv + ((size_t)b*C3 + 2*CCH + (size_t)h*CH) * HW + s0;
  float acc[8][4] = {};
  for (int d = 0; d < CH; d++) {
    float vv[4];
    #pragma unroll
    for (int j = 0; j < 4; j++) vv[j] = V[(size_t)d*HW + t + j*256];
    #pragma unroll
    for (int ci = 0; ci < 8; ci++) {
      float a = a_s[ci][d];
      #pragma unroll
      for (int j = 0; j < 4; j++) acc[ci][j] += a * vv[j];
    }
  }
  float* O = out + ((size_t)b*CCH + h*CH + cg*8) * HW + s0;
  #pragma unroll
  for (int ci = 0; ci < 8; ci++)
    #pragma unroll
    for (int j = 0; j < 4; j++)
      O[(size_t)ci*HW + t + j*256] = acc[ci][j];
}

// ---------------- launch -----------------------------------------------------
extern "C" void kernel_launch(void* const* d_in, const int* in_sizes, int n_in,
                              void* d_out, int out_size)
{
  const float* x        = (const float*)d_in[0];
  const float* cn       = (const float*)d_in[1];
  const float* cn_w1    = (const float*)d_in[2];
  const float* cn_w3    = (const float*)d_in[3];
  const float* qkv_w    = (const float*)d_in[4];
  const float* qkv_dw_w = (const float*)d_in[5];
  const float* proj_w   = (const float*)d_in[6];
  const float* temp     = (const float*)d_in[7];
  float* out = (float*)d_out;

  float *cn1, *cnf, *qkv1, *qkv, *qf, *kn, *av, *al, *be, *ik, *Lp, *at;
  cudaGetSymbolAddress((void**)&cn1,  g_cn1);
  cudaGetSymbolAddress((void**)&cnf,  g_cnf);
  cudaGetSymbolAddress((void**)&qkv1, g_qkv1);
  cudaGetSymbolAddress((void**)&qkv,  g_qkv);
  cudaGetSymbolAddress((void**)&qf,   g_qf);
  cudaGetSymbolAddress((void**)&kn,   g_kn);
  cudaGetSymbolAddress((void**)&av,   g_av);
  cudaGetSymbolAddress((void**)&al,   g_alpha);
  cudaGetSymbolAddress((void**)&be,   g_beta);
  cudaGetSymbolAddress((void**)&ik,   g_invk);
  cudaGetSymbolAddress((void**)&Lp,   g_Lpart);
  cudaGetSymbolAddress((void**)&at,   g_attn);

  dim3 g1(HW/64, CCH/64, NB);       // (256,3,8)
  gemm1x1_k<<<g1, 256>>>(cn_w1, cn, cn1, CCH, CCH);
  conv3x3_k<<<g1, 256>>>(cn_w3, cn1, cnf);

  dim3 g2(HW/64, C3/64, NB);        // (256,9,8)
  gemm1x1_k<<<g2, 256>>>(qkv_w, x, qkv1, C3, CCH);

  size_t ndw = (size_t)NB * C3 * HW;
  dwconv3_k<<<(unsigned)(ndw / 256), 256>>>(qkv1, qkv_dw_w, qkv);

  rownorms_k<<<dim3(CCH, NB), 256>>>(qkv, cnf, al, be, ik);

  size_t nel = (size_t)NB * CCH * HW;
  make_qfkn_k<<<(unsigned)(nel / 256), 256>>>(qkv, cnf, al, be, ik, qf, kn);

  logits_k<<<dim3(16, NB*NHEAD), 256>>>(qf, kn, Lp);
  softmax_k<<<NB*NHEAD*CH, 32>>>(Lp, temp, at);
  attnv_k<<<dim3(16, 6, NB*NHEAD), 256>>>(qkv, at, av);

  gemm1x1_k<<<g1, 256>>>(proj_w, av, out, CCH, CCH);
}

// round 4
// speedup vs baseline: 2.9158x; 2.9158x over previous
#include <cuda_runtime.h>
#include <math.h>

#define HW    16384
#define WID   128
#define CCH   192
#define C3    576
#define NB    8
#define NHEAD 4
#define CH    48
#define EPSV  1e-12f

// ---------------- scratch (device globals; allocation-free) ----------------
__device__ __align__(16) float g_cn1 [(size_t)NB*CCH*HW];  // conv1x1(cn)
__device__ __align__(16) float g_cnf [(size_t)NB*CCH*HW];  // conv3x3(g_cn1)
__device__ __align__(16) float g_qkv1[(size_t)NB*C3 *HW];  // conv1x1(x)
__device__ __align__(16) float g_qkv [(size_t)NB*C3 *HW];  // depthwise(g_qkv1)
__device__ __align__(16) float g_av  [(size_t)NB*CCH*HW];  // attn @ v
__device__ float g_alpha[NB*CCH];
__device__ float g_beta [NB*CCH];
__device__ float g_invk [NB*CCH];
__device__ float g_Lpart[(size_t)16*NB*NHEAD*CH*CH];       // deterministic partials
__device__ float g_attn [(size_t)NB*NHEAD*CH*CH];

__device__ __forceinline__ unsigned f2tf(float f) {
  unsigned u; asm("cvt.rna.tf32.f32 %0, %1;" : "=r"(u) : "f"(f)); return u;
}
__device__ __forceinline__ void mma_tf32(float* c, const unsigned* a, const unsigned* b) {
  asm volatile(
    "mma.sync.aligned.m16n8k8.row.col.f32.tf32.tf32.f32 "
    "{%0,%1,%2,%3},{%4,%5,%6,%7},{%8,%9},{%0,%1,%2,%3};"
    : "+f"(c[0]), "+f"(c[1]), "+f"(c[2]), "+f"(c[3])
    : "r"(a[0]), "r"(a[1]), "r"(a[2]), "r"(a[3]), "r"(b[0]), "r"(b[1]));
}

// ====================== tf32 tensor-core GEMM (1x1 conv) ====================
// Y[b,m,n] = sum_k W[m,k] X[b,k,n].  CTA tile 192(M) x 128(N), BK=16.
// 8 warps as 4(m) x 2(n); warp tile 48x64 (3 x 8 mma tiles of m16n8k8).
#define AST 200   // As row stride (mod 32 == 8 -> conflict-free frag loads)
#define BST 136   // Bs row stride (mod 32 == 8)

__global__ __launch_bounds__(256, 1) void gemm1x1_tc(
    const float* __restrict__ Wm, const float* __restrict__ X,
    float* __restrict__ Y, int M, int K)
{
  const int b  = blockIdx.z;
  const int m0 = blockIdx.y * 192;
  const int n0 = blockIdx.x * 128;
  const float* Xb = X + (size_t)b * K * HW;
  float* Yb = Y + (size_t)b * M * HW;

  __shared__ unsigned As[16][AST];
  __shared__ unsigned Bs[16][BST];

  const int t    = threadIdx.x;
  const int wid  = t >> 5, lane = t & 31;
  const int wm   = wid >> 1, wn = wid & 1;
  const int grp  = lane >> 2, t4 = lane & 3;

  float acc[3][8][4] = {};

  // ---- preload tile k0 = 0 ----
  float4 pa[3], pb[2];
  #pragma unroll
  for (int i = 0; i < 3; i++) {
    int e = t + i * 256; int row = e >> 2, kf = (e & 3) * 4;
    pa[i] = *(const float4*)&Wm[(size_t)(m0 + row) * K + kf];
  }
  #pragma unroll
  for (int i = 0; i < 2; i++) {
    int e = t + i * 256; int kk = e >> 5, nf = e & 31;
    pb[i] = *(const float4*)&Xb[(size_t)kk * HW + n0 + nf * 4];
  }
  #pragma unroll
  for (int i = 0; i < 3; i++) {
    int e = t + i * 256; int row = e >> 2, kf = (e & 3) * 4;
    As[kf+0][row]=f2tf(pa[i].x); As[kf+1][row]=f2tf(pa[i].y);
    As[kf+2][row]=f2tf(pa[i].z); As[kf+3][row]=f2tf(pa[i].w);
  }
  #pragma unroll
  for (int i = 0; i < 2; i++) {
    int e = t + i * 256; int kk = e >> 5, nf = e & 31;
    Bs[kk][nf*4+0]=f2tf(pb[i].x); Bs[kk][nf*4+1]=f2tf(pb[i].y);
    Bs[kk][nf*4+2]=f2tf(pb[i].z); Bs[kk][nf*4+3]=f2tf(pb[i].w);
  }
  __syncthreads();

  for (int k0 = 0; k0 < K; k0 += 16) {
    // prefetch next
    bool more = (k0 + 16) < K;
    if (more) {
      #pragma unroll
      for (int i = 0; i < 3; i++) {
        int e = t + i * 256; int row = e >> 2, kf = (e & 3) * 4;
        pa[i] = *(const float4*)&Wm[(size_t)(m0 + row) * K + k0 + 16 + kf];
      }
      #pragma unroll
      for (int i = 0; i < 2; i++) {
        int e = t + i * 256; int kk = e >> 5, nf = e & 31;
        pb[i] = *(const float4*)&Xb[(size_t)(k0 + 16 + kk) * HW + n0 + nf * 4];
      }
    }
    // compute
    #pragma unroll
    for (int ks = 0; ks < 16; ks += 8) {
      unsigned af[3][4], bf[8][2];
      #pragma unroll
      for (int mt = 0; mt < 3; mt++) {
        int mb = wm * 48 + mt * 16 + grp;
        af[mt][0] = As[ks + t4][mb];     af[mt][1] = As[ks + t4][mb + 8];
        af[mt][2] = As[ks + t4 + 4][mb]; af[mt][3] = As[ks + t4 + 4][mb + 8];
      }
      #pragma unroll
      for (int nt = 0; nt < 8; nt++) {
        int nb = wn * 64 + nt * 8 + grp;
        bf[nt][0] = Bs[ks + t4][nb]; bf[nt][1] = Bs[ks + t4 + 4][nb];
      }
      #pragma unroll
      for (int mt = 0; mt < 3; mt++)
        #pragma unroll
        for (int nt = 0; nt < 8; nt++)
          mma_tf32(acc[mt][nt], af[mt], bf[nt]);
    }
    __syncthreads();
    if (more) {
      #pragma unroll
      for (int i = 0; i < 3; i++) {
        int e = t + i * 256; int row = e >> 2, kf = (e & 3) * 4;
        As[kf+0][row]=f2tf(pa[i].x); As[kf+1][row]=f2tf(pa[i].y);
        As[kf+2][row]=f2tf(pa[i].z); As[kf+3][row]=f2tf(pa[i].w);
      }
      #pragma unroll
      for (int i = 0; i < 2; i++) {
        int e = t + i * 256; int kk = e >> 5, nf = e & 31;
        Bs[kk][nf*4+0]=f2tf(pb[i].x); Bs[kk][nf*4+1]=f2tf(pb[i].y);
        Bs[kk][nf*4+2]=f2tf(pb[i].z); Bs[kk][nf*4+3]=f2tf(pb[i].w);
      }
      __syncthreads();
    }
  }

  #pragma unroll
  for (int mt = 0; mt < 3; mt++) {
    #pragma unroll
    for (int nt = 0; nt < 8; nt++) {
      int mr = m0 + wm * 48 + mt * 16 + grp;
      int nc = n0 + wn * 64 + nt * 8 + t4 * 2;
      *(float2*)&Yb[(size_t)mr * HW + nc] = make_float2(acc[mt][nt][0], acc[mt][nt][1]);
      *(float2*)&Yb[(size_t)(mr + 8) * HW + nc] = make_float2(acc[mt][nt][2], acc[mt][nt][3]);
    }
  }
}

// =============== tf32 tensor-core implicit-GEMM 3x3 conv ====================
// K = 192*9 = 1728. N tile = 128 = one full image row (y = blockIdx.x).
__global__ __launch_bounds__(256, 1) void conv3x3_tc(
    const float* __restrict__ Wm, const float* __restrict__ X,
    float* __restrict__ Y)
{
  const int Ktot = CCH * 9;
  const int b = blockIdx.z;
  const int y = blockIdx.x;           // image row; n0 = y*128
  const float* Xb = X + (size_t)b * CCH * HW;
  float* Yb = Y + (size_t)b * CCH * HW;

  __shared__ unsigned As[16][AST];
  __shared__ unsigned Bs[16][BST];

  const int t   = threadIdx.x;
  const int wid = t >> 5, lane = t & 31;
  const int wm  = wid >> 1, wn = wid & 1;
  const int grp = lane >> 2, t4 = lane & 3;

  float acc[3][8][4] = {};

  float4 pa[3];
  float  pbv[2][4];

  // im2col gather of B tile row kk (global k), 4 floats starting at col nf*4
  auto gatherB = [&](int kglob, int nf, float* o) {
    int ci = kglob / 9;
    int r  = kglob - ci * 9;
    int dy = r / 3 - 1;
    int dx = r - (r / 3) * 3 - 1;
    int yy = y + dy;
    bool rowok = (yy >= 0) & (yy < WID);
    const float* src = Xb + (size_t)ci * HW + yy * WID;
    #pragma unroll
    for (int j = 0; j < 4; j++) {
      int xx = nf * 4 + j + dx;
      o[j] = (rowok && xx >= 0 && xx < WID) ? src[xx] : 0.f;
    }
  };

  // ---- preload k0=0 ----
  #pragma unroll
  for (int i = 0; i < 3; i++) {
    int e = t + i * 256; int row = e >> 2, kf = (e & 3) * 4;
    pa[i] = *(const float4*)&Wm[(size_t)row * Ktot + kf];
  }
  #pragma unroll
  for (int i = 0; i < 2; i++) {
    int e = t + i * 256; int kk = e >> 5, nf = e & 31;
    gatherB(kk, nf, pbv[i]);
  }
  #pragma unroll
  for (int i = 0; i < 3; i++) {
    int e = t + i * 256; int row = e >> 2, kf = (e & 3) * 4;
    As[kf+0][row]=f2tf(pa[i].x); As[kf+1][row]=f2tf(pa[i].y);
    As[kf+2][row]=f2tf(pa[i].z); As[kf+3][row]=f2tf(pa[i].w);
  }
  #pragma unroll
  for (int i = 0; i < 2; i++) {
    int e = t + i * 256; int kk = e >> 5, nf = e & 31;
    #pragma unroll
    for (int j = 0; j < 4; j++) Bs[kk][nf*4+j] = f2tf(pbv[i][j]);
  }
  __syncthreads();

  for (int k0 = 0; k0 < Ktot; k0 += 16) {
    bool more = (k0 + 16) < Ktot;
    if (more) {
      #pragma unroll
      for (int i = 0; i < 3; i++) {
        int e = t + i * 256; int row = e >> 2, kf = (e & 3) * 4;
        pa[i] = *(const float4*)&Wm[(size_t)row * Ktot + k0 + 16 + kf];
      }
      #pragma unroll
      for (int i = 0; i < 2; i++) {
        int e = t + i * 256; int kk = e >> 5, nf = e & 31;
        gatherB(k0 + 16 + kk, nf, pbv[i]);
      }
    }
    #pragma unroll
    for (int ks = 0; ks < 16; ks += 8) {
      unsigned af[3][4], bf[8][2];
      #pragma unroll
      for (int mt = 0; mt < 3; mt++) {
        int mb = wm * 48 + mt * 16 + grp;
        af[mt][0] = As[ks + t4][mb];     af[mt][1] = As[ks + t4][mb + 8];
        af[mt][2] = As[ks + t4 + 4][mb]; af[mt][3] = As[ks + t4 + 4][mb + 8];
      }
      #pragma unroll
      for (int nt = 0; nt < 8; nt++) {
        int nb = wn * 64 + nt * 8 + grp;
        bf[nt][0] = Bs[ks + t4][nb]; bf[nt][1] = Bs[ks + t4 + 4][nb];
      }
      #pragma unroll
      for (int mt = 0; mt < 3; mt++)
        #pragma unroll
        for (int nt = 0; nt < 8; nt++)
          mma_tf32(acc[mt][nt], af[mt], bf[nt]);
    }
    __syncthreads();
    if (more) {
      #pragma unroll
      for (int i = 0; i < 3; i++) {
        int e = t + i * 256; int row = e >> 2, kf = (e & 3) * 4;
        As[kf+0][row]=f2tf(pa[i].x); As[kf+1][row]=f2tf(pa[i].y);
        As[kf+2][row]=f2tf(pa[i].z); As[kf+3][row]=f2tf(pa[i].w);
      }
      #pragma unroll
      for (int i = 0; i < 2; i++) {
        int e = t + i * 256; int kk = e >> 5, nf = e & 31;
        #pragma unroll
        for (int j = 0; j < 4; j++) Bs[kk][nf*4+j] = f2tf(pbv[i][j]);
      }
      __syncthreads();
    }
  }

  const int n0 = y * 128;
  #pragma unroll
  for (int mt = 0; mt < 3; mt++) {
    #pragma unroll
    for (int nt = 0; nt < 8; nt++) {
      int mr = wm * 48 + mt * 16 + grp;
      int nc = n0 + wn * 64 + nt * 8 + t4 * 2;
      *(float2*)&Yb[(size_t)mr * HW + nc] = make_float2(acc[mt][nt][0], acc[mt][nt][1]);
      *(float2*)&Yb[(size_t)(mr + 8) * HW + nc] = make_float2(acc[mt][nt][2], acc[mt][nt][3]);
    }
  }
}

// ---------------- depthwise 3x3 (groups = 3C), 4 outputs/thread -------------
__global__ __launch_bounds__(256) void dwconv4_k(
    const float* __restrict__ in, const float* __restrict__ w,
    float* __restrict__ out)
{
  size_t i4 = (size_t)blockIdx.x * 256 + threadIdx.x;   // NB*C3*HW/4 threads
  size_t base = i4 * 4;
  int s  = (int)(base & (HW - 1));
  size_t bc = base >> 14;
  int c = (int)(bc % C3);
  int y = s >> 7, x0 = s & 127;
  const float* wp = w + (size_t)c * 9;
  const float* ip = in + (base - s);
  float w0=wp[0],w1=wp[1],w2=wp[2],w3=wp[3],w4=wp[4],w5=wp[5],w6=wp[6],w7=wp[7],w8=wp[8];
  float a0=0,a1=0,a2=0,a3=0;
  #pragma unroll
  for (int dy = -1; dy <= 1; dy++) {
    int yy = y + dy;
    if (yy < 0 || yy >= WID) continue;
    const float* row = ip + yy * WID;
    float4 cv = *(const float4*)&row[x0];
    float lf = (x0 > 0)   ? row[x0 - 1] : 0.f;
    float rt = (x0 < 124) ? row[x0 + 4] : 0.f;
    float r0, r1, r2;
    if (dy < 0)      { r0 = w0; r1 = w1; r2 = w2; }
    else if (dy==0)  { r0 = w3; r1 = w4; r2 = w5; }
    else             { r0 = w6; r1 = w7; r2 = w8; }
    a0 += r0*lf   + r1*cv.x + r2*cv.y;
    a1 += r0*cv.x + r1*cv.y + r2*cv.z;
    a2 += r0*cv.y + r1*cv.z + r2*cv.w;
    a3 += r0*cv.z + r1*cv.w + r2*rt;
  }
  *(float4*)&out[base] = make_float4(a0, a1, a2, a3);
}

// ---------------- per-(b,c) norms + fold double-normalize into scalars -----
__global__ __launch_bounds__(256) void rownorms_k(
    const float* __restrict__ qkv, const float* __restrict__ cnf,
    float* __restrict__ alpha, float* __restrict__ beta,
    float* __restrict__ invk)
{
  int c = blockIdx.x, b = blockIdx.y;
  const float* q  = qkv + ((size_t)b*C3 + c) * HW;
  const float* k  = qkv + ((size_t)b*C3 + CCH + c) * HW;
  const float* cn = cnf + ((size_t)b*CCH + c) * HW;
  float sq = 0, sk = 0, sc = 0, sd = 0;
  for (int s4 = threadIdx.x; s4 < HW/4; s4 += 256) {
    float4 qv = *(const float4*)&q[s4*4];
    float4 kv = *(const float4*)&k[s4*4];
    float4 cv = *(const float4*)&cn[s4*4];
    sq += qv.x*qv.x+qv.y*qv.y+qv.z*qv.z+qv.w*qv.w;
    sk += kv.x*kv.x+kv.y*kv.y+kv.z*kv.z+kv.w*kv.w;
    sc += cv.x*cv.x+cv.y*cv.y+cv.z*cv.z+cv.w*cv.w;
    sd += qv.x*cv.x+qv.y*cv.y+qv.z*cv.z+qv.w*cv.w;
  }
  #pragma unroll
  for (int o = 16; o > 0; o >>= 1) {
    sq += __shfl_down_sync(0xffffffffu, sq, o);
    sk += __shfl_down_sync(0xffffffffu, sk, o);
    sc += __shfl_down_sync(0xffffffffu, sc, o);
    sd += __shfl_down_sync(0xffffffffu, sd, o);
  }
  __shared__ float red[4][8];
  int lane = threadIdx.x & 31, wd = threadIdx.x >> 5;
  if (lane == 0) { red[0][wd]=sq; red[1][wd]=sk; red[2][wd]=sc; red[3][wd]=sd; }
  __syncthreads();
  if (threadIdx.x == 0) {
    float Sq=0, Sk=0, Sc=0, Sd=0;
    for (int i = 0; i < 8; i++) { Sq+=red[0][i]; Sk+=red[1][i]; Sc+=red[2][i]; Sd+=red[3][i]; }
    float a  = fmaxf(sqrtf(Sq), EPSV);
    float bb = fmaxf(sqrtf(Sc), EPSV);
    float n2 = Sq/(a*a) + 2.f*Sd/(a*bb) + Sc/(bb*bb);   // ||q/a + cn/bb||^2
    float dn = fmaxf(sqrtf(fmaxf(n2, 0.f)), EPSV);
    int bc = b*CCH + c;
    alpha[bc] = 1.f / (a * dn);
    beta [bc] = 1.f / (bb * dn);
    invk [bc] = 1.f / fmaxf(sqrtf(Sk), EPSV);
  }
}

// ---------------- logits partials with fused scaling -----------------------
// L[c,d] = sum_s (al[c]*q[c,s]+be[c]*cn[c,s]) * (ik[d]*k[d,s])
__global__ __launch_bounds__(256) void logits_k(
    const float* __restrict__ qkv, const float* __restrict__ cnf,
    const float* __restrict__ alpha, const float* __restrict__ beta,
    const float* __restrict__ invk, float* __restrict__ Lpart)
{
  int bh = blockIdx.y; int b = bh >> 2, h = bh & 3;
  int chunk = blockIdx.x;
  int s0 = chunk * 1024;
  const float* Q  = qkv + ((size_t)b*C3 + h*CH) * HW;
  const float* Kp = qkv + ((size_t)b*C3 + CCH + h*CH) * HW;
  const float* Cn = cnf + ((size_t)b*CCH + h*CH) * HW;
  __shared__ float Qs[48][68];
  __shared__ float Ks[48][68];
  __shared__ float sAl[48], sBe[48], sIk[48];
  const int t = threadIdx.x;
  if (t < 48) {
    int ch = b*CCH + h*CH + t;
    sAl[t] = alpha[ch]; sBe[t] = beta[ch]; sIk[t] = invk[ch];
  }
  __syncthreads();
  const int tx = t & 15, ty = t >> 4;
  float acc[3][3] = {};
  for (int sc = 0; sc < 1024; sc += 64) {
    #pragma unroll
    for (int i = 0; i < 3; i++) {
      int e = t + i * 256;
      int row = e >> 4;
      int col = (e & 15) * 4;
      float4 q4 = *(const float4*)&Q [(size_t)row*HW + s0 + sc + col];
      float4 c4 = *(const float4*)&Cn[(size_t)row*HW + s0 + sc + col];
      float4 k4 = *(const float4*)&Kp[(size_t)row*HW + s0 + sc + col];
      float al = sAl[row], be = sBe[row], ik = sIk[row];
      Qs[row][col+0] = al*q4.x + be*c4.x;
      Qs[row][col+1] = al*q4.y + be*c4.y;
      Qs[row][col+2] = al*q4.z + be*c4.z;
      Qs[row][col+3] = al*q4.w + be*c4.w;
      Ks[row][col+0] = ik*k4.x; Ks[row][col+1] = ik*k4.y;
      Ks[row][col+2] = ik*k4.z; Ks[row][col+3] = ik*k4.w;
    }
    __syncthreads();
    #pragma unroll 8
    for (int s = 0; s < 64; s++) {
      float qv0 = Qs[ty*3+0][s], qv1 = Qs[ty*3+1][s], qv2 = Qs[ty*3+2][s];
      float kv0 = Ks[tx*3+0][s], kv1 = Ks[tx*3+1][s], kv2 = Ks[tx*3+2][s];
      acc[0][0]+=qv0*kv0; acc[0][1]+=qv0*kv1; acc[0][2]+=qv0*kv2;
      acc[1][0]+=qv1*kv0; acc[1][1]+=qv1*kv1; acc[1][2]+=qv1*kv2;
      acc[2][0]+=qv2*kv0; acc[2][1]+=qv2*kv1; acc[2][2]+=qv2*kv2;
    }
    __syncthreads();
  }
  float* Lp = Lpart + (((size_t)chunk * 32 + bh) * CH) * CH;
  #pragma unroll
  for (int i = 0; i < 3; i++)
    #pragma unroll
    for (int j = 0; j < 3; j++)
      Lp[(size_t)(ty*3+i)*CH + tx*3+j] = acc[i][j];
}

// ---------------- reduce partials + temperature + softmax over d ------------
__global__ __launch_bounds__(32) void softmax_k(
    const float* __restrict__ Lpart, const float* __restrict__ temp,
    float* __restrict__ attn)
{
  int row = blockIdx.x;            // bh*48 + c
  int bh = row / CH;
  int c  = row - bh * CH;
  int h  = bh & 3;
  int lane = threadIdx.x;
  float tv = temp[h];
  float v0 = 0.f, v1 = 0.f;
  bool has1 = (lane + 32) < CH;
  for (int ch = 0; ch < 16; ch++) {
    const float* p = Lpart + (((size_t)ch*32 + bh)*CH + c)*CH;
    v0 += p[lane];
    if (has1) v1 += p[lane + 32];
  }
  v0 *= tv; v1 *= tv;
  float m = has1 ? fmaxf(v0, v1) : v0;
  #pragma unroll
  for (int o = 16; o > 0; o >>= 1) m = fmaxf(m, __shfl_xor_sync(0xffffffffu, m, o));
  float e0 = __expf(v0 - m);
  float e1 = has1 ? __expf(v1 - m) : 0.f;
  float s = e0 + e1;
  #pragma unroll
  for (int o = 16; o > 0; o >>= 1) s += __shfl_xor_sync(0xffffffffu, s, o);
  float inv = 1.f / s;
  attn[(size_t)row*CH + lane] = e0 * inv;
  if (has1) attn[(size_t)row*CH + lane + 32] = e1 * inv;
}

// ---------------- out[c,s] = sum_d attn[c,d] * v[d,s] -----------------------
__global__ __launch_bounds__(256) void attnv_k(
    const float* __restrict__ qkv, const float* __restrict__ attn,
    float* __restrict__ out)
{
  int bh = blockIdx.z; int b = bh >> 2, h = bh & 3;
  int cg = blockIdx.y;             // 0..5 -> 8 channels each
  int s0 = blockIdx.x * 1024;
  __shared__ float a_s[8][48];
  const int t = threadIdx.x;
  for (int e = t; e < 8*48; e += 256)
    a_s[e/48][e%48] = attn[((size_t)bh*CH + cg*8 + e/48)*CH + (e%48)];
  __syncthreads();
  const float* V = qkv + ((size_t)b*C3 + 2*CCH + (size_t)h*CH) * HW + s0;
  float acc[8][4] = {};
  for (int d = 0; d < CH; d++) {
    float vv[4];
    #pragma unroll
    for (int j = 0; j < 4; j++) vv[j] = V[(size_t)d*HW + t + j*256];
    #pragma unroll
    for (int ci = 0; ci < 8; ci++) {
      float a = a_s[ci][d];
      #pragma unroll
      for (int j = 0; j < 4; j++) acc[ci][j] += a * vv[j];
    }
  }
  float* O = out + ((size_t)b*CCH + h*CH + cg*8) * HW + s0;
  #pragma unroll
  for (int ci = 0; ci < 8; ci++)
    #pragma unroll
    for (int j = 0; j < 4; j++)
      O[(size_t)ci*HW + t + j*256] = acc[ci][j];
}

// ---------------- launch -----------------------------------------------------
extern "C" void kernel_launch(void* const* d_in, const int* in_sizes, int n_in,
                              void* d_out, int out_size)
{
  const float* x        = (const float*)d_in[0];
  const float* cn       = (const float*)d_in[1];
  const float* cn_w1    = (const float*)d_in[2];
  const float* cn_w3    = (const float*)d_in[3];
  const float* qkv_w    = (const float*)d_in[4];
  const float* qkv_dw_w = (const float*)d_in[5];
  const float* proj_w   = (const float*)d_in[6];
  const float* temp     = (const float*)d_in[7];
  float* out = (float*)d_out;

  float *cn1, *cnf, *qkv1, *qkv, *av, *al, *be, *ik, *Lp, *at;
  cudaGetSymbolAddress((void**)&cn1,  g_cn1);
  cudaGetSymbolAddress((void**)&cnf,  g_cnf);
  cudaGetSymbolAddress((void**)&qkv1, g_qkv1);
  cudaGetSymbolAddress((void**)&qkv,  g_qkv);
  cudaGetSymbolAddress((void**)&av,   g_av);
  cudaGetSymbolAddress((void**)&al,   g_alpha);
  cudaGetSymbolAddress((void**)&be,   g_beta);
  cudaGetSymbolAddress((void**)&ik,   g_invk);
  cudaGetSymbolAddress((void**)&Lp,   g_Lpart);
  cudaGetSymbolAddress((void**)&at,   g_attn);

  dim3 g1(HW/128, 1, NB);           // (128,1,8) for M=192
  gemm1x1_tc<<<g1, 256>>>(cn_w1, cn, cn1, CCH, CCH);
  conv3x3_tc<<<g1, 256>>>(cn_w3, cn1, cnf);

  dim3 g2(HW/128, 3, NB);           // (128,3,8) for M=576
  gemm1x1_tc<<<g2, 256>>>(qkv_w, x, qkv1, C3, CCH);

  size_t ndw4 = (size_t)NB * C3 * HW / 4;
  dwconv4_k<<<(unsigned)(ndw4 / 256), 256>>>(qkv1, qkv_dw_w, qkv);

  rownorms_k<<<dim3(CCH, NB), 256>>>(qkv, cnf, al, be, ik);

  logits_k<<<dim3(16, NB*NHEAD), 256>>>(qkv, cnf, al, be, ik, Lp);
  softmax_k<<<NB*NHEAD*CH, 32>>>(Lp, temp, at);
  attnv_k<<<dim3(16, 6, NB*NHEAD), 256>>>(qkv, at, av);

  gemm1x1_tc<<<g1, 256>>>(proj_w, av, out, CCH, CCH);
}

// round 6
// speedup vs baseline: 3.4007x; 1.1663x over previous
#include <cuda_runtime.h>
#include <cuda_fp16.h>
#include <math.h>
#include <stdint.h>

#define HW    16384
#define WID   128
#define CCH   192
#define C3    576
#define NB    8
#define NHEAD 4
#define CH    48
#define EPSV  1e-12f

// ---------------- scratch (device globals; allocation-free) ----------------
__device__ __align__(16) float g_cn1 [(size_t)NB*CCH*HW];
__device__ __align__(16) float g_cnf [(size_t)NB*CCH*HW];
__device__ __align__(16) float g_qkv1[(size_t)NB*C3 *HW];
__device__ __align__(16) float g_qkv [(size_t)NB*C3 *HW];
__device__ __align__(16) float g_av  [(size_t)NB*CCH*HW];
__device__ float g_alpha[NB*CCH];
__device__ float g_beta [NB*CCH];
__device__ float g_invk [NB*CCH];
__device__ float g_Lpart[(size_t)16*NB*NHEAD*CH*CH];
__device__ float g_attn [(size_t)NB*NHEAD*CH*CH];

__device__ __forceinline__ uint32_t pack_h2(float lo, float hi) {
  __half2 h = __floats2half2_rn(lo, hi);
  return *(uint32_t*)&h;
}
__device__ __forceinline__ void mma_fp16(float* c, const uint32_t* a, const uint32_t* b) {
  asm volatile(
    "mma.sync.aligned.m16n8k16.row.col.f32.f16.f16.f32 "
    "{%0,%1,%2,%3},{%4,%5,%6,%7},{%8,%9},{%0,%1,%2,%3};"
    : "+f"(c[0]), "+f"(c[1]), "+f"(c[2]), "+f"(c[3])
    : "r"(a[0]), "r"(a[1]), "r"(a[2]), "r"(a[3]), "r"(b[0]), "r"(b[1]));
}

// ================ fp16 tensor-core GEMM (1x1 conv) ==========================
// Y[b,m,n] = sum_k W[m,k] X[b,k,n].  CTA tile 192(M) x 128(N), BK=16.
// 8 warps 4(m) x 2(n); warp tile 48x64 = 3 x 8 mma tiles of m16n8k16.
// As2[k2][m]: half2 packs (k,k+1) of W row m.  Bs2[k2][n]: packs (k,k+1) of col n.
#define AST 200   // % 32 == 8 -> conflict-free fragment loads
#define BST 136

__global__ __launch_bounds__(256, 1) void gemm1x1_fp16(
    const float* __restrict__ Wm, const float* __restrict__ X,
    float* __restrict__ Y, int M, int K)
{
  const int b  = blockIdx.z;
  const int m0 = blockIdx.y * 192;
  const int n0 = blockIdx.x * 128;
  const float* Xb = X + (size_t)b * K * HW;
  float* Yb = Y + (size_t)b * M * HW;

  __shared__ uint32_t As2[8][AST];
  __shared__ uint32_t Bs2[8][BST];

  const int t    = threadIdx.x;
  const int wid  = t >> 5, lane = t & 31;
  const int wm   = wid >> 1, wn = wid & 1;
  const int grp  = lane >> 2, t4 = lane & 3;

  float acc[3][8][4] = {};

  const int bk2 = t >> 5;          // 0..7   (B fill k2)
  const int bng = (t & 31) * 4;    // 0..124 (B fill n group)

  float4 pa[3], pb0, pb1;
  // ---- preload k0 = 0 ----
  #pragma unroll
  for (int i = 0; i < 3; i++) {
    int e = t + i * 256; int row = e >> 2, kf = (e & 3) * 4;
    pa[i] = *(const float4*)&Wm[(size_t)(m0 + row) * K + kf];
  }
  pb0 = *(const float4*)&Xb[(size_t)(2 * bk2    ) * HW + n0 + bng];
  pb1 = *(const float4*)&Xb[(size_t)(2 * bk2 + 1) * HW + n0 + bng];
  #pragma unroll
  for (int i = 0; i < 3; i++) {
    int e = t + i * 256; int row = e >> 2, k2 = (e & 3) * 2;
    As2[k2  ][row] = pack_h2(pa[i].x, pa[i].y);
    As2[k2+1][row] = pack_h2(pa[i].z, pa[i].w);
  }
  {
    uint4 u = make_uint4(pack_h2(pb0.x, pb1.x), pack_h2(pb0.y, pb1.y),
                         pack_h2(pb0.z, pb1.z), pack_h2(pb0.w, pb1.w));
    *(uint4*)&Bs2[bk2][bng] = u;
  }
  __syncthreads();

  for (int k0 = 0; k0 < K; k0 += 16) {
    bool more = (k0 + 16) < K;
    if (more) {
      #pragma unroll
      for (int i = 0; i < 3; i++) {
        int e = t + i * 256; int row = e >> 2, kf = (e & 3) * 4;
        pa[i] = *(const float4*)&Wm[(size_t)(m0 + row) * K + k0 + 16 + kf];
      }
      pb0 = *(const float4*)&Xb[(size_t)(k0 + 16 + 2 * bk2    ) * HW + n0 + bng];
      pb1 = *(const float4*)&Xb[(size_t)(k0 + 16 + 2 * bk2 + 1) * HW + n0 + bng];
    }
    // ---- compute: one m16n8k16 per (mt, nt) covers full BK=16 ----
    {
      uint32_t af[3][4], bf[8][2];
      #pragma unroll
      for (int mt = 0; mt < 3; mt++) {
        int mb = wm * 48 + mt * 16 + grp;
        af[mt][0] = As2[t4    ][mb];     af[mt][1] = As2[t4    ][mb + 8];
        af[mt][2] = As2[t4 + 4][mb];     af[mt][3] = As2[t4 + 4][mb + 8];
      }
      #pragma unroll
      for (int nt = 0; nt < 8; nt++) {
        int nb = wn * 64 + nt * 8 + grp;
        bf[nt][0] = Bs2[t4][nb]; bf[nt][1] = Bs2[t4 + 4][nb];
      }
      #pragma unroll
      for (int mt = 0; mt < 3; mt++)
        #pragma unroll
        for (int nt = 0; nt < 8; nt++)
          mma_fp16(acc[mt][nt], af[mt], bf[nt]);
    }
    __syncthreads();
    if (more) {
      #pragma unroll
      for (int i = 0; i < 3; i++) {
        int e = t + i * 256; int row = e >> 2, k2 = (e & 3) * 2;
        As2[k2  ][row] = pack_h2(pa[i].x, pa[i].y);
        As2[k2+1][row] = pack_h2(pa[i].z, pa[i].w);
      }
      uint4 u = make_uint4(pack_h2(pb0.x, pb1.x), pack_h2(pb0.y, pb1.y),
                           pack_h2(pb0.z, pb1.z), pack_h2(pb0.w, pb1.w));
      *(uint4*)&Bs2[bk2][bng] = u;
      __syncthreads();
    }
  }

  #pragma unroll
  for (int mt = 0; mt < 3; mt++) {
    #pragma unroll
    for (int nt = 0; nt < 8; nt++) {
      int mr = m0 + wm * 48 + mt * 16 + grp;
      int nc = n0 + wn * 64 + nt * 8 + t4 * 2;
      *(float2*)&Yb[(size_t)mr * HW + nc] = make_float2(acc[mt][nt][0], acc[mt][nt][1]);
      *(float2*)&Yb[(size_t)(mr + 8) * HW + nc] = make_float2(acc[mt][nt][2], acc[mt][nt][3]);
    }
  }
}

// ============= fp16 tensor-core implicit-GEMM 3x3 conv ======================
// K = 192*9 = 1728. N tile = 128 = one full image row (y = blockIdx.x).
__global__ __launch_bounds__(256, 1) void conv3x3_fp16(
    const float* __restrict__ Wm, const float* __restrict__ X,
    float* __restrict__ Y)
{
  const int Ktot = CCH * 9;
  const int b = blockIdx.z;
  const int y = blockIdx.x;
  const float* Xb = X + (size_t)b * CCH * HW;
  float* Yb = Y + (size_t)b * CCH * HW;

  __shared__ uint32_t As2[8][AST];
  __shared__ uint32_t Bs2[8][BST];

  const int t   = threadIdx.x;
  const int wid = t >> 5, lane = t & 31;
  const int wm  = wid >> 1, wn = wid & 1;
  const int grp = lane >> 2, t4 = lane & 3;

  float acc[3][8][4] = {};

  const int bk2 = t >> 5;
  const int bng = (t & 31) * 4;

  // gather 4 consecutive-x values of im2col row kglob starting at x=bng
  auto gatherB = [&](int kglob, float* o) {
    int ci = kglob / 9;
    int r  = kglob - ci * 9;
    int ky = r / 3;
    int kx = r - ky * 3;
    int yy = y + ky - 1;
    bool rowok = (yy >= 0) & (yy < WID);
    const float* src = Xb + (size_t)ci * HW + yy * WID;
    #pragma unroll
    for (int j = 0; j < 4; j++) {
      int xx = bng + j + kx - 1;
      o[j] = (rowok && xx >= 0 && xx < WID) ? src[xx] : 0.f;
    }
  };

  float4 pa[3];
  float pb0[4], pb1[4];
  #pragma unroll
  for (int i = 0; i < 3; i++) {
    int e = t + i * 256; int row = e >> 2, kf = (e & 3) * 4;
    pa[i] = *(const float4*)&Wm[(size_t)row * Ktot + kf];
  }
  gatherB(2 * bk2, pb0);
  gatherB(2 * bk2 + 1, pb1);
  #pragma unroll
  for (int i = 0; i < 3; i++) {
    int e = t + i * 256; int row = e >> 2, k2 = (e & 3) * 2;
    As2[k2  ][row] = pack_h2(pa[i].x, pa[i].y);
    As2[k2+1][row] = pack_h2(pa[i].z, pa[i].w);
  }
  {
    uint4 u = make_uint4(pack_h2(pb0[0], pb1[0]), pack_h2(pb0[1], pb1[1]),
                         pack_h2(pb0[2], pb1[2]), pack_h2(pb0[3], pb1[3]));
    *(uint4*)&Bs2[bk2][bng] = u;
  }
  __syncthreads();

  for (int k0 = 0; k0 < Ktot; k0 += 16) {
    bool more = (k0 + 16) < Ktot;
    if (more) {
      #pragma unroll
      for (int i = 0; i < 3; i++) {
        int e = t + i * 256; int row = e >> 2, kf = (e & 3) * 4;
        pa[i] = *(const float4*)&Wm[(size_t)row * Ktot + k0 + 16 + kf];
      }
      gatherB(k0 + 16 + 2 * bk2, pb0);
      gatherB(k0 + 16 + 2 * bk2 + 1, pb1);
    }
    {
      uint32_t af[3][4], bf[8][2];
      #pragma unroll
      for (int mt = 0; mt < 3; mt++) {
        int mb = wm * 48 + mt * 16 + grp;
        af[mt][0] = As2[t4    ][mb];     af[mt][1] = As2[t4    ][mb + 8];
        af[mt][2] = As2[t4 + 4][mb];     af[mt][3] = As2[t4 + 4][mb + 8];
      }
      #pragma unroll
      for (int nt = 0; nt < 8; nt++) {
        int nb = wn * 64 + nt * 8 + grp;
        bf[nt][0] = Bs2[t4][nb]; bf[nt][1] = Bs2[t4 + 4][nb];
      }
      #pragma unroll
      for (int mt = 0; mt < 3; mt++)
        #pragma unroll
        for (int nt = 0; nt < 8; nt++)
          mma_fp16(acc[mt][nt], af[mt], bf[nt]);
    }
    __syncthreads();
    if (more) {
      #pragma unroll
      for (int i = 0; i < 3; i++) {
        int e = t + i * 256; int row = e >> 2, k2 = (e & 3) * 2;
        As2[k2  ][row] = pack_h2(pa[i].x, pa[i].y);
        As2[k2+1][row] = pack_h2(pa[i].z, pa[i].w);
      }
      uint4 u = make_uint4(pack_h2(pb0[0], pb1[0]), pack_h2(pb0[1], pb1[1]),
                           pack_h2(pb0[2], pb1[2]), pack_h2(pb0[3], pb1[3]));
      *(uint4*)&Bs2[bk2][bng] = u;
      __syncthreads();
    }
  }

  const int n0 = y * 128;
  #pragma unroll
  for (int mt = 0; mt < 3; mt++) {
    #pragma unroll
    for (int nt = 0; nt < 8; nt++) {
      int mr = wm * 48 + mt * 16 + grp;
      int nc = n0 + wn * 64 + nt * 8 + t4 * 2;
      *(float2*)&Yb[(size_t)mr * HW + nc] = make_float2(acc[mt][nt][0], acc[mt][nt][1]);
      *(float2*)&Yb[(size_t)(mr + 8) * HW + nc] = make_float2(acc[mt][nt][2], acc[mt][nt][3]);
    }
  }
}

// ---------------- depthwise 3x3 (groups = 3C), 4 outputs/thread -------------
__global__ __launch_bounds__(256) void dwconv4_k(
    const float* __restrict__ in, const float* __restrict__ w,
    float* __restrict__ out)
{
  size_t i4 = (size_t)blockIdx.x * 256 + threadIdx.x;
  size_t base = i4 * 4;
  int s  = (int)(base & (HW - 1));
  size_t bc = base >> 14;
  int c = (int)(bc % C3);
  int y = s >> 7, x0 = s & 127;
  const float* wp = w + (size_t)c * 9;
  const float* ip = in + (base - s);
  float w0=wp[0],w1=wp[1],w2=wp[2],w3=wp[3],w4=wp[4],w5=wp[5],w6=wp[6],w7=wp[7],w8=wp[8];
  float a0=0,a1=0,a2=0,a3=0;
  #pragma unroll
  for (int dy = -1; dy <= 1; dy++) {
    int yy = y + dy;
    if (yy < 0 || yy >= WID) continue;
    const float* row = ip + yy * WID;
    float4 cv = *(const float4*)&row[x0];
    float lf = (x0 > 0)   ? row[x0 - 1] : 0.f;
    float rt = (x0 < 124) ? row[x0 + 4] : 0.f;
    float r0, r1, r2;
    if (dy < 0)      { r0 = w0; r1 = w1; r2 = w2; }
    else if (dy==0)  { r0 = w3; r1 = w4; r2 = w5; }
    else             { r0 = w6; r1 = w7; r2 = w8; }
    a0 += r0*lf   + r1*cv.x + r2*cv.y;
    a1 += r0*cv.x + r1*cv.y + r2*cv.z;
    a2 += r0*cv.y + r1*cv.z + r2*cv.w;
    a3 += r0*cv.z + r1*cv.w + r2*rt;
  }
  *(float4*)&out[base] = make_float4(a0, a1, a2, a3);
}

// ---------------- per-(b,c) norms + fold double-normalize into scalars -----
__global__ __launch_bounds__(256) void rownorms_k(
    const float* __restrict__ qkv, const float* __restrict__ cnf,
    float* __restrict__ alpha, float* __restrict__ beta,
    float* __restrict__ invk)
{
  int c = blockIdx.x, b = blockIdx.y;
  const float* q  = qkv + ((size_t)b*C3 + c) * HW;
  const float* k  = qkv + ((size_t)b*C3 + CCH + c) * HW;
  const float* cn = cnf + ((size_t)b*CCH + c) * HW;
  float sq = 0, sk = 0, sc = 0, sd = 0;
  for (int s4 = threadIdx.x; s4 < HW/4; s4 += 256) {
    float4 qv = *(const float4*)&q[s4*4];
    float4 kv = *(const float4*)&k[s4*4];
    float4 cv = *(const float4*)&cn[s4*4];
    sq += qv.x*qv.x+qv.y*qv.y+qv.z*qv.z+qv.w*qv.w;
    sk += kv.x*kv.x+kv.y*kv.y+kv.z*kv.z+kv.w*kv.w;
    sc += cv.x*cv.x+cv.y*cv.y+cv.z*cv.z+cv.w*cv.w;
    sd += qv.x*cv.x+qv.y*cv.y+qv.z*cv.z+qv.w*cv.w;
  }
  #pragma unroll
  for (int o = 16; o > 0; o >>= 1) {
    sq += __shfl_down_sync(0xffffffffu, sq, o);
    sk += __shfl_down_sync(0xffffffffu, sk, o);
    sc += __shfl_down_sync(0xffffffffu, sc, o);
    sd += __shfl_down_sync(0xffffffffu, sd, o);
  }
  __shared__ float red[4][8];
  int lane = threadIdx.x & 31, wd = threadIdx.x >> 5;
  if (lane == 0) { red[0][wd]=sq; red[1][wd]=sk; red[2][wd]=sc; red[3][wd]=sd; }
  __syncthreads();
  if (threadIdx.x == 0) {
    float Sq=0, Sk=0, Sc=0, Sd=0;
    for (int i = 0; i < 8; i++) { Sq+=red[0][i]; Sk+=red[1][i]; Sc+=red[2][i]; Sd+=red[3][i]; }
    float a  = fmaxf(sqrtf(Sq), EPSV);
    float bb = fmaxf(sqrtf(Sc), EPSV);
    float n2 = Sq/(a*a) + 2.f*Sd/(a*bb) + Sc/(bb*bb);
    float dn = fmaxf(sqrtf(fmaxf(n2, 0.f)), EPSV);
    int bc = b*CCH + c;
    alpha[bc] = 1.f / (a * dn);
    beta [bc] = 1.f / (bb * dn);
    invk [bc] = 1.f / fmaxf(sqrtf(Sk), EPSV);
  }
}

// ---------------- logits partials with fused scaling -----------------------
__global__ __launch_bounds__(256) void logits_k(
    const float* __restrict__ qkv, const float* __restrict__ cnf,
    const float* __restrict__ alpha, const float* __restrict__ beta,
    const float* __restrict__ invk, float* __restrict__ Lpart)
{
  int bh = blockIdx.y; int b = bh >> 2, h = bh & 3;
  int chunk = blockIdx.x;
  int s0 = chunk * 1024;
  const float* Q  = qkv + ((size_t)b*C3 + h*CH) * HW;
  const float* Kp = qkv + ((size_t)b*C3 + CCH + h*CH) * HW;
  const float* Cn = cnf + ((size_t)b*CCH + h*CH) * HW;
  __shared__ float Qs[48][68];
  __shared__ float Ks[48][68];
  __shared__ float sAl[48], sBe[48], sIk[48];
  const int t = threadIdx.x;
  if (t < 48) {
    int ch = b*CCH + h*CH + t;
    sAl[t] = alpha[ch]; sBe[t] = beta[ch]; sIk[t] = invk[ch];
  }
  __syncthreads();
  const int tx = t & 15, ty = t >> 4;
  float acc[3][3] = {};
  for (int sc = 0; sc < 1024; sc += 64) {
    #pragma unroll
    for (int i = 0; i < 3; i++) {
      int e = t + i * 256;
      int row = e >> 4;
      int col = (e & 15) * 4;
      float4 q4 = *(const float4*)&Q [(size_t)row*HW + s0 + sc + col];
      float4 c4 = *(const float4*)&Cn[(size_t)row*HW + s0 + sc + col];
      float4 k4 = *(const float4*)&Kp[(size_t)row*HW + s0 + sc + col];
      float al = sAl[row], be = sBe[row], ik = sIk[row];
      Qs[row][col+0] = al*q4.x + be*c4.x;
      Qs[row][col+1] = al*q4.y + be*c4.y;
      Qs[row][col+2] = al*q4.z + be*c4.z;
      Qs[row][col+3] = al*q4.w + be*c4.w;
      Ks[row][col+0] = ik*k4.x; Ks[row][col+1] = ik*k4.y;
      Ks[row][col+2] = ik*k4.z; Ks[row][col+3] = ik*k4.w;
    }
    __syncthreads();
    #pragma unroll 8
    for (int s = 0; s < 64; s++) {
      float qv0 = Qs[ty*3+0][s], qv1 = Qs[ty*3+1][s], qv2 = Qs[ty*3+2][s];
      float kv0 = Ks[tx*3+0][s], kv1 = Ks[tx*3+1][s], kv2 = Ks[tx*3+2][s];
      acc[0][0]+=qv0*kv0; acc[0][1]+=qv0*kv1; acc[0][2]+=qv0*kv2;
      acc[1][0]+=qv1*kv0; acc[1][1]+=qv1*kv1; acc[1][2]+=qv1*kv2;
      acc[2][0]+=qv2*kv0; acc[2][1]+=qv2*kv1; acc[2][2]+=qv2*kv2;
    }
    __syncthreads();
  }
  float* Lp = Lpart + (((size_t)chunk * 32 + bh) * CH) * CH;
  #pragma unroll
  for (int i = 0; i < 3; i++)
    #pragma unroll
    for (int j = 0; j < 3; j++)
      Lp[(size_t)(ty*3+i)*CH + tx*3+j] = acc[i][j];
}

// ---------------- reduce partials + temperature + softmax over d ------------
__global__ __launch_bounds__(32) void softmax_k(
    const float* __restrict__ Lpart, const float* __restrict__ temp,
    float* __restrict__ attn)
{
  int row = blockIdx.x;
  int bh = row / CH;
  int c  = row - bh * CH;
  int h  = bh & 3;
  int lane = threadIdx.x;
  float tv = temp[h];
  float v0 = 0.f, v1 = 0.f;
  bool has1 = (lane + 32) < CH;
  for (int ch = 0; ch < 16; ch++) {
    const float* p = Lpart + (((size_t)ch*32 + bh)*CH + c)*CH;
    v0 += p[lane];
    if (has1) v1 += p[lane + 32];
  }
  v0 *= tv; v1 *= tv;
  float m = has1 ? fmaxf(v0, v1) : v0;
  #pragma unroll
  for (int o = 16; o > 0; o >>= 1) m = fmaxf(m, __shfl_xor_sync(0xffffffffu, m, o));
  float e0 = __expf(v0 - m);
  float e1 = has1 ? __expf(v1 - m) : 0.f;
  float s = e0 + e1;
  #pragma unroll
  for (int o = 16; o > 0; o >>= 1) s += __shfl_xor_sync(0xffffffffu, s, o);
  float inv = 1.f / s;
  attn[(size_t)row*CH + lane] = e0 * inv;
  if (has1) attn[(size_t)row*CH + lane + 32] = e1 * inv;
}

// ---------------- out[c,s] = sum_d attn[c,d] * v[d,s] -----------------------
__global__ __launch_bounds__(256) void attnv_k(
    const float* __restrict__ qkv, const float* __restrict__ attn,
    float* __restrict__ out)
{
  int bh = blockIdx.z; int b = bh >> 2, h = bh & 3;
  int cg = blockIdx.y;
  int s0 = blockIdx.x * 1024;
  __shared__ float a_s[8][48];
  const int t = threadIdx.x;
  for (int e = t; e < 8*48; e += 256)
    a_s[e/48][e%48] = attn[((size_t)bh*CH + cg*8 + e/48)*CH + (e%48)];
  __syncthreads();
  const float* V = qkv + ((size_t)b*C3 + 2*CCH + (size_t)h*CH) * HW + s0;
  float acc[8][4] = {};
  for (int d = 0; d < CH; d++) {
    float vv[4];
    #pragma unroll
    for (int j = 0; j < 4; j++) vv[j] = V[(size_t)d*HW + t + j*256];
    #pragma unroll
    for (int ci = 0; ci < 8; ci++) {
      float a = a_s[ci][d];
      #pragma unroll
      for (int j = 0; j < 4; j++) acc[ci][j] += a * vv[j];
    }
  }
  float* O = out + ((size_t)b*CCH + h*CH + cg*8) * HW + s0;
  #pragma unroll
  for (int ci = 0; ci < 8; ci++)
    #pragma unroll
    for (int j = 0; j < 4; j++)
      O[(size_t)ci*HW + t + j*256] = acc[ci][j];
}

// ---------------- launch -----------------------------------------------------
extern "C" void kernel_launch(void* const* d_in, const int* in_sizes, int n_in,
                              void* d_out, int out_size)
{
  const float* x        = (const float*)d_in[0];
  const float* cn       = (const float*)d_in[1];
  const float* cn_w1    = (const float*)d_in[2];
  const float* cn_w3    = (const float*)d_in[3];
  const float* qkv_w    = (const float*)d_in[4];
  const float* qkv_dw_w = (const float*)d_in[5];
  const float* proj_w   = (const float*)d_in[6];
  const float* temp     = (const float*)d_in[7];
  float* out = (float*)d_out;

  float *cn1, *cnf, *qkv1, *qkv, *av, *al, *be, *ik, *Lp, *at;
  cudaGetSymbolAddress((void**)&cn1,  g_cn1);
  cudaGetSymbolAddress((void**)&cnf,  g_cnf);
  cudaGetSymbolAddress((void**)&qkv1, g_qkv1);
  cudaGetSymbolAddress((void**)&qkv,  g_qkv);
  cudaGetSymbolAddress((void**)&av,   g_av);
  cudaGetSymbolAddress((void**)&al,   g_alpha);
  cudaGetSymbolAddress((void**)&be,   g_beta);
  cudaGetSymbolAddress((void**)&ik,   g_invk);
  cudaGetSymbolAddress((void**)&Lp,   g_Lpart);
  cudaGetSymbolAddress((void**)&at,   g_attn);

  dim3 g1(HW/128, 1, NB);           // M=192
  gemm1x1_fp16<<<g1, 256>>>(cn_w1, cn, cn1, CCH, CCH);
  conv3x3_fp16<<<g1, 256>>>(cn_w3, cn1, cnf);

  dim3 g2(HW/128, 3, NB);           // M=576
  gemm1x1_fp16<<<g2, 256>>>(qkv_w, x, qkv1, C3, CCH);

  size_t ndw4 = (size_t)NB * C3 * HW / 4;
  dwconv4_k<<<(unsigned)(ndw4 / 256), 256>>>(qkv1, qkv_dw_w, qkv);

  rownorms_k<<<dim3(CCH, NB), 256>>>(qkv, cnf, al, be, ik);

  logits_k<<<dim3(16, NB*NHEAD), 256>>>(qkv, cnf, al, be, ik, Lp);
  softmax_k<<<NB*NHEAD*CH, 32>>>(Lp, temp, at);
  attnv_k<<<dim3(16, 6, NB*NHEAD), 256>>>(qkv, at, av);

  gemm1x1_fp16<<<g1, 256>>>(proj_w, av, out, CCH, CCH);
}